// round 16
// baseline (speedup 1.0000x reference)
#include <cuda_runtime.h>

#define EDIM 512
#define HDIM 256
#define QN   1024
#define SN   512
#define NSTEP 3

// ---------------- scratch (no allocations allowed) ----------------
__device__ float g_tmp[(QN + SN) * HDIM];   // hidden of encoder MLP
__device__ float g_enc[(QN + SN) * HDIM];   // q rows [0,1024), s rows [1024,1536)
__device__ float g_A[SN * HDIM];
__device__ float g_Bm[SN * HDIM];
__device__ float g_Hagg[SN * HDIM];
__device__ float g_hq[QN * HDIM];
__device__ float g_hs[SN * HDIM];
__device__ float g_rdenom[SN];
__device__ float g_flag[SN];

__device__ __forceinline__ void qbar(int q) {
    // decoupled 128-thread barrier per K-quarter (warp-aligned groups)
    asm volatile("bar.sync %0, %1;" :: "r"(q + 1), "r"(128) : "memory");
}

// dynamic-smem layout (floats):
//   As: [q][buf][k16][m32]   q*1024 + buf*512 + k*32 + m          (0..4096)
//   Bs: [q][buf][k16][n64]   4096 + q*2048 + buf*1024 + k*64 + n  (4096..12288)
//   red: 3*128*16            12288..18432
//   ws (scores only): [q][buf][k16]  18432 + q*32 + buf*16 + k    (18432..18560)
#define SM_BS   4096
#define SM_RED  12288
#define SM_WS   18432
#define GEMM_SMEM_BYTES  (18432 * 4)
#define SCORE_SMEM_BYTES (18560 * 4)

// ---------------- generic fp32 GEMM: C = A(MxK) @ B(KxN=256) ----------------
// 32x64 block tile, 512 threads = 4 K-quarters x 128, 4x4 micro-tile,
// double-buffered smem, register-pipelined LDS, deterministic 4-way reduction.
struct GArgs {
    const float* A0; const float* A1;
    const float* B0; const float* B1;
    float* C0; float* C1;
    const float* bias0; const float* bias1;
    int M0, M1, K;
};

template <int RELU, int ACCUM, int ROWFLAG>
__global__ __launch_bounds__(512) void gemm_k(GArgs g) {
    extern __shared__ float smem[];
    const int z = blockIdx.z;
    const float* A    = z ? g.A1 : g.A0;
    const float* B    = z ? g.B1 : g.B0;
    float*       C    = z ? g.C1 : g.C0;
    const float* bias = z ? g.bias1 : g.bias0;
    const int M = z ? g.M1 : g.M0;
    const int K = g.K;

    const int m0 = blockIdx.y * 32;
    if (m0 >= M) return;
    const int n0 = blockIdx.x * 64;

    const int tid = threadIdx.x;
    const int q   = tid >> 7;             // K-quarter 0..3
    const int t   = tid & 127;
    const int tx = t & 15, ty = t >> 4;   // 4x4 micro-tile: rows 4*ty, cols 4*tx
    const int lr = t & 31, lc4 = t >> 5;  // A staging: row lr, k-cols 4*lc4
    const int bk = t >> 4,  bn4 = t & 15; // B staging: k-rows bk & bk+8, cols 4*bn4

    const int K4     = K >> 2;
    const int kbase  = q * K4;
    const int ntiles = K4 >> 4;

    float* As  = smem + q * 1024;
    float* Bs  = smem + SM_BS + q * 2048;
    float* red = smem + SM_RED;

    // prologue: tile 0 -> buf 0
    {
        float4 av  = *(const float4*)(A + (m0 + lr) * K + kbase + 4 * lc4);
        float4 bv0 = *(const float4*)(B + (kbase + bk) * HDIM + n0 + 4 * bn4);
        float4 bv1 = *(const float4*)(B + (kbase + bk + 8) * HDIM + n0 + 4 * bn4);
        As[(4 * lc4 + 0) * 32 + lr] = av.x;
        As[(4 * lc4 + 1) * 32 + lr] = av.y;
        As[(4 * lc4 + 2) * 32 + lr] = av.z;
        As[(4 * lc4 + 3) * 32 + lr] = av.w;
        *(float4*)&Bs[bk * 64 + 4 * bn4]       = bv0;
        *(float4*)&Bs[(bk + 8) * 64 + 4 * bn4] = bv1;
        qbar(q);
    }

    float acc[4][4] = {};

    for (int it = 0; it < ntiles; it++) {
        const int bufA = (it & 1) * 512;
        const int bufB = (it & 1) * 1024;

        // prefetch next tile globals into registers
        float4 av2, bv2a, bv2b;
        const bool more = (it + 1 < ntiles);
        if (more) {
            const int k0 = kbase + (it + 1) * 16;
            av2  = *(const float4*)(A + (m0 + lr) * K + k0 + 4 * lc4);
            bv2a = *(const float4*)(B + (k0 + bk) * HDIM + n0 + 4 * bn4);
            bv2b = *(const float4*)(B + (k0 + bk + 8) * HDIM + n0 + 4 * bn4);
        }

        // register-pipelined smem mainloop
        float4 a_cur = *(const float4*)&As[bufA + 0 * 32 + ty * 4];
        float4 b_cur = *(const float4*)&Bs[bufB + 0 * 64 + tx * 4];
#pragma unroll
        for (int kk = 0; kk < 16; kk++) {
            float4 a_nxt = a_cur;
            float4 b_nxt = b_cur;
            if (kk < 15) {
                a_nxt = *(const float4*)&As[bufA + (kk + 1) * 32 + ty * 4];
                b_nxt = *(const float4*)&Bs[bufB + (kk + 1) * 64 + tx * 4];
            }
            float a[4] = {a_cur.x, a_cur.y, a_cur.z, a_cur.w};
            float b[4] = {b_cur.x, b_cur.y, b_cur.z, b_cur.w};
#pragma unroll
            for (int r = 0; r < 4; r++)
#pragma unroll
                for (int c = 0; c < 4; c++) acc[r][c] += a[r] * b[c];
            a_cur = a_nxt;
            b_cur = b_nxt;
        }

        if (more) {
            const int nbA = ((it + 1) & 1) * 512;
            const int nbB = ((it + 1) & 1) * 1024;
            As[nbA + (4 * lc4 + 0) * 32 + lr] = av2.x;
            As[nbA + (4 * lc4 + 1) * 32 + lr] = av2.y;
            As[nbA + (4 * lc4 + 2) * 32 + lr] = av2.z;
            As[nbA + (4 * lc4 + 3) * 32 + lr] = av2.w;
            *(float4*)&Bs[nbB + bk * 64 + 4 * bn4]       = bv2a;
            *(float4*)&Bs[nbB + (bk + 8) * 64 + 4 * bn4] = bv2b;
            qbar(q);
        }
    }

    // deterministic 4-way reduction: q1..q3 store, q0 adds in fixed order
    __syncthreads();
    if (q > 0) {
        float* rp = red + (q - 1) * 2048 + t * 16;
#pragma unroll
        for (int r = 0; r < 4; r++)
            *(float4*)(rp + 4 * r) = make_float4(acc[r][0], acc[r][1], acc[r][2], acc[r][3]);
    }
    __syncthreads();
    if (q > 0) return;

#pragma unroll
    for (int p = 0; p < 3; p++) {
        const float* rp = red + p * 2048 + t * 16;
#pragma unroll
        for (int r = 0; r < 4; r++) {
            float4 v = *(const float4*)(rp + 4 * r);
            acc[r][0] += v.x; acc[r][1] += v.y; acc[r][2] += v.z; acc[r][3] += v.w;
        }
    }

    const int m = m0 + ty * 4;
    const int n = n0 + tx * 4;
    float bb[4] = {0.f, 0.f, 0.f, 0.f};
    if (bias) {
        bb[0] = bias[n]; bb[1] = bias[n + 1]; bb[2] = bias[n + 2]; bb[3] = bias[n + 3];
    }
#pragma unroll
    for (int r = 0; r < 4; r++) {
        const float fl = ROWFLAG ? g_flag[m + r] : 1.0f;
        float v[4];
#pragma unroll
        for (int c = 0; c < 4; c++) v[c] = acc[r][c] + bb[c] * fl;
        if (ACCUM) {
            float4 cv = *(const float4*)(C + (m + r) * HDIM + n);
            v[0] += cv.x; v[1] += cv.y; v[2] += cv.z; v[3] += cv.w;
        }
        if (RELU) {
#pragma unroll
            for (int c = 0; c < 4; c++) v[c] = fmaxf(v[c], 0.f);
        }
        *(float4*)(C + (m + r) * HDIM + n) = make_float4(v[0], v[1], v[2], v[3]);
    }
}

// ---------------- per-support-point class counts ----------------
__global__ void cnt_k(const int* __restrict__ y) {
    __shared__ int ys[SN];
    int t = threadIdx.x;          // 512 threads
    ys[t] = y[t];
    __syncthreads();
    int yi = ys[t];
    int c = 0;
    for (int j = 0; j < SN; j++) c += (ys[j] == yi);
    c -= 1;                        // exclude self
    g_rdenom[t] = 1.0f / fmaxf((float)c, 1.0f);
    g_flag[t]   = (c > 0) ? 1.0f : 0.0f;
}

// ---------------- masked relu-sum aggregation ----------------
// Hagg[i] = (1/denom_i) * sum_{j: y_j==y_i, j!=i} relu(A[i] + B[j] + bm1t)
__global__ __launch_bounds__(256) void hagg_k(const int* __restrict__ y,
                                              const float* __restrict__ bm1t) {
    const int i = blockIdx.x;
    __shared__ int   ys[SN];
    __shared__ short list[SN];
    __shared__ int   s_cnt;

    const int t = threadIdx.x;     // 256 threads
    ys[t]       = y[t];
    ys[t + 256] = y[t + 256];
    __syncthreads();

    const int yi = ys[i];
    if (t < 32) {                  // warp 0 builds a deterministic, ascending list
        int cnt = 0;
        for (int it = 0; it < SN / 32; it++) {
            int j = it * 32 + t;
            bool m = (ys[j] == yi) && (j != i);
            unsigned mask = __ballot_sync(0xffffffffu, m);
            if (m) {
                int pos = cnt + __popc(mask & ((1u << t) - 1u));
                list[pos] = (short)j;
            }
            cnt += __popc(mask);
        }
        if (t == 0) s_cnt = cnt;
    }
    __syncthreads();

    const int cnt = s_cnt;
    const float ai = g_A[i * HDIM + t] + bm1t[t];
    float acc = 0.f;
    int l = 0;
    for (; l + 4 <= cnt; l += 4) {           // MLP=4 against L2 latency
        int j0 = list[l], j1 = list[l + 1], j2 = list[l + 2], j3 = list[l + 3];
        float v0 = g_Bm[j0 * HDIM + t];
        float v1 = g_Bm[j1 * HDIM + t];
        float v2 = g_Bm[j2 * HDIM + t];
        float v3 = g_Bm[j3 * HDIM + t];
        acc += fmaxf(ai + v0, 0.f);
        acc += fmaxf(ai + v1, 0.f);
        acc += fmaxf(ai + v2, 0.f);
        acc += fmaxf(ai + v3, 0.f);
    }
    for (; l < cnt; l++) {
        int j = list[l];
        acc += fmaxf(ai + g_Bm[j * HDIM + t], 0.f);
    }
    g_Hagg[i * HDIM + t] = acc * g_rdenom[i];
}

// ---------------- final relation scores ----------------
// scores[i][j] = sum_h relu(hq[i][h] + hs[j][h]) * wr2[h] + br2
// 32x64 tile, 512 threads = 4 K-quarters x 128, 4x4 micro-tile.
__global__ __launch_bounds__(512) void scores_k(const float* __restrict__ wr2,
                                                const float* __restrict__ br2p,
                                                float* __restrict__ out) {
    extern __shared__ float smem[];
    const int m0 = blockIdx.y * 32;   // query rows
    const int n0 = blockIdx.x * 64;   // support cols
    const int tid = threadIdx.x;
    const int q   = tid >> 7;
    const int t   = tid & 127;
    const int tx = t & 15, ty = t >> 4;
    const int lr = t & 31, lc4 = t >> 5;
    const int bk = t >> 4,  bn4 = t & 15;

    const int K4     = HDIM >> 2;   // 64
    const int kbase  = q * K4;
    const int ntiles = K4 >> 4;     // 4

    float* As  = smem + q * 1024;
    float* Bs  = smem + SM_BS + q * 2048;
    float* red = smem + SM_RED;
    float* ws  = smem + SM_WS + q * 32;

    // prologue (B tile here is hs rows: Bs[k][j] = hs[n0+j][kbase+k])
    {
        float4 av = *(const float4*)(g_hq + (m0 + lr) * HDIM + kbase + 4 * lc4);
        As[(4 * lc4 + 0) * 32 + lr] = av.x;
        As[(4 * lc4 + 1) * 32 + lr] = av.y;
        As[(4 * lc4 + 2) * 32 + lr] = av.z;
        As[(4 * lc4 + 3) * 32 + lr] = av.w;
        // hs staging: thread loads hs[n0 + 2*bn4 + {0,1}][kbase + 4*? ] — use row-major gather:
        // simpler: each thread loads float4 of hs for 2 (row, kgroup) pairs matching Bs[k][n]
        // Bs[k][n] = hs[n0+n][kbase+k]; stage via 128 threads x 8 elems:
        // thread covers n = 2*bk + (bn4>>3), k-cols 4*(bn4&7) ... to keep simple use scalar-free float4:
        // n index: jn = t >> 4 (0..7) *8 rows? -- replaced below by loop
        (void)bk; (void)bn4;
        for (int e = t; e < 16 * 64 / 4; e += 128) {     // 256 float4 slots
            int kq = e >> 4;          // 0..15 (k)
            int n4 = e & 15;          // 0..15 (n/4)
            // load hs[n0+4*n4 .. +3][kbase+kq] -> 4 scalars (strided gather)
            float v0 = g_hs[(n0 + 4 * n4 + 0) * HDIM + kbase + kq];
            float v1 = g_hs[(n0 + 4 * n4 + 1) * HDIM + kbase + kq];
            float v2 = g_hs[(n0 + 4 * n4 + 2) * HDIM + kbase + kq];
            float v3 = g_hs[(n0 + 4 * n4 + 3) * HDIM + kbase + kq];
            *(float4*)&Bs[kq * 64 + 4 * n4] = make_float4(v0, v1, v2, v3);
        }
        if (t < 16) ws[t] = wr2[kbase + t];
        qbar(q);
    }

    float acc[4][4] = {};

    for (int it = 0; it < ntiles; it++) {
        const int bufA = (it & 1) * 512;
        const int bufB = (it & 1) * 1024;
        const int bufW = (it & 1) * 16;

        float4 av2;
        float bsv[8];
        float wv2 = 0.f;
        const bool more = (it + 1 < ntiles);
        int e0 = 0;
        if (more) {
            const int k0 = kbase + (it + 1) * 16;
            av2 = *(const float4*)(g_hq + (m0 + lr) * HDIM + k0 + 4 * lc4);
            // prefetch the strided hs gather (2 float4 slots per thread)
#pragma unroll
            for (int s = 0; s < 2; s++) {
                int e = t + s * 128;
                int kq = e >> 4, n4 = e & 15;
                bsv[s * 4 + 0] = g_hs[(n0 + 4 * n4 + 0) * HDIM + k0 + kq];
                bsv[s * 4 + 1] = g_hs[(n0 + 4 * n4 + 1) * HDIM + k0 + kq];
                bsv[s * 4 + 2] = g_hs[(n0 + 4 * n4 + 2) * HDIM + k0 + kq];
                bsv[s * 4 + 3] = g_hs[(n0 + 4 * n4 + 3) * HDIM + k0 + kq];
            }
            if (t < 16) wv2 = wr2[k0 + t];
            e0 = 1;
        }
        (void)e0;

        float4 a_cur = *(const float4*)&As[bufA + 0 * 32 + ty * 4];
        float4 b_cur = *(const float4*)&Bs[bufB + 0 * 64 + tx * 4];
        float  w_cur = ws[bufW + 0];
#pragma unroll
        for (int kk = 0; kk < 16; kk++) {
            float4 a_nxt = a_cur;
            float4 b_nxt = b_cur;
            float  w_nxt = w_cur;
            if (kk < 15) {
                a_nxt = *(const float4*)&As[bufA + (kk + 1) * 32 + ty * 4];
                b_nxt = *(const float4*)&Bs[bufB + (kk + 1) * 64 + tx * 4];
                w_nxt = ws[bufW + kk + 1];
            }
            float a[4] = {a_cur.x, a_cur.y, a_cur.z, a_cur.w};
            float b[4] = {b_cur.x, b_cur.y, b_cur.z, b_cur.w};
#pragma unroll
            for (int r = 0; r < 4; r++)
#pragma unroll
                for (int c = 0; c < 4; c++)
                    acc[r][c] += fmaxf(a[r] + b[c], 0.f) * w_cur;
            a_cur = a_nxt; b_cur = b_nxt; w_cur = w_nxt;
        }

        if (more) {
            const int nbA = ((it + 1) & 1) * 512;
            const int nbB = ((it + 1) & 1) * 1024;
            const int nbW = ((it + 1) & 1) * 16;
            As[nbA + (4 * lc4 + 0) * 32 + lr] = av2.x;
            As[nbA + (4 * lc4 + 1) * 32 + lr] = av2.y;
            As[nbA + (4 * lc4 + 2) * 32 + lr] = av2.z;
            As[nbA + (4 * lc4 + 3) * 32 + lr] = av2.w;
#pragma unroll
            for (int s = 0; s < 2; s++) {
                int e = t + s * 128;
                int kq = e >> 4, n4 = e & 15;
                *(float4*)&Bs[nbB + kq * 64 + 4 * n4] =
                    make_float4(bsv[s * 4 + 0], bsv[s * 4 + 1], bsv[s * 4 + 2], bsv[s * 4 + 3]);
            }
            if (t < 16) ws[nbW + t] = wv2;
            qbar(q);
        }
    }

    __syncthreads();
    if (q > 0) {
        float* rp = red + (q - 1) * 2048 + t * 16;
#pragma unroll
        for (int r = 0; r < 4; r++)
            *(float4*)(rp + 4 * r) = make_float4(acc[r][0], acc[r][1], acc[r][2], acc[r][3]);
    }
    __syncthreads();
    if (q > 0) return;

#pragma unroll
    for (int p = 0; p < 3; p++) {
        const float* rp = red + p * 2048 + t * 16;
#pragma unroll
        for (int r = 0; r < 4; r++) {
            float4 v = *(const float4*)(rp + 4 * r);
            acc[r][0] += v.x; acc[r][1] += v.y; acc[r][2] += v.z; acc[r][3] += v.w;
        }
    }

    const float br2 = br2p[0];
    const int m = m0 + ty * 4;
    const int n = n0 + tx * 4;
#pragma unroll
    for (int r = 0; r < 4; r++) {
        *(float4*)(out + (m + r) * SN + n) =
            make_float4(acc[r][0] + br2, acc[r][1] + br2, acc[r][2] + br2, acc[r][3] + br2);
    }
}

// ---------------- host launcher ----------------
extern "C" void kernel_launch(void* const* d_in, const int* in_sizes, int n_in,
                              void* d_out, int out_size) {
    (void)in_sizes; (void)n_in; (void)out_size;
    const float* qf  = (const float*)d_in[0];
    const float* sf  = (const float*)d_in[1];
    const int*   y   = (const int*)  d_in[2];
    const float* Wn1 = (const float*)d_in[3];
    const float* bn1 = (const float*)d_in[4];
    const float* Wn2 = (const float*)d_in[5];
    const float* bn2 = (const float*)d_in[6];
    const float* Wm1 = (const float*)d_in[7];
    const float* bm1 = (const float*)d_in[8];
    const float* Wm2 = (const float*)d_in[9];
    const float* bm2 = (const float*)d_in[10];
    const float* Wr1 = (const float*)d_in[11];
    const float* br1 = (const float*)d_in[12];
    const float* wr2 = (const float*)d_in[13];
    const float* br2 = (const float*)d_in[14];
    float* out = (float*)d_out;

    float *tmp, *enc, *Abuf, *Bbuf, *Hg, *hq, *hs;
    cudaGetSymbolAddress((void**)&tmp,  g_tmp);
    cudaGetSymbolAddress((void**)&enc,  g_enc);
    cudaGetSymbolAddress((void**)&Abuf, g_A);
    cudaGetSymbolAddress((void**)&Bbuf, g_Bm);
    cudaGetSymbolAddress((void**)&Hg,   g_Hagg);
    cudaGetSymbolAddress((void**)&hq,   g_hq);
    cudaGetSymbolAddress((void**)&hs,   g_hs);

    cudaFuncSetAttribute(gemm_k<1, 0, 0>, cudaFuncAttributeMaxDynamicSharedMemorySize, GEMM_SMEM_BYTES);
    cudaFuncSetAttribute(gemm_k<0, 0, 0>, cudaFuncAttributeMaxDynamicSharedMemorySize, GEMM_SMEM_BYTES);
    cudaFuncSetAttribute(gemm_k<0, 1, 1>, cudaFuncAttributeMaxDynamicSharedMemorySize, GEMM_SMEM_BYTES);
    cudaFuncSetAttribute(scores_k,        cudaFuncAttributeMaxDynamicSharedMemorySize, SCORE_SMEM_BYTES);

    float* qenc = enc;                 // rows [0, 1024)
    float* senc = enc + QN * HDIM;     // rows [1024, 1536)

    // class counts (once)
    cnt_k<<<1, SN>>>(y);

    // encoder layer 1: relu([Qf;Sf] @ Wn1 + bn1) -> g_tmp   (fused q/s via z)
    {
        GArgs a = {qf, sf, Wn1, Wn1, tmp, tmp + QN * HDIM, bn1, bn1, QN, SN, EDIM};
        gemm_k<1, 0, 0><<<dim3(HDIM / 64, QN / 32, 2), 512, GEMM_SMEM_BYTES>>>(a);
    }
    // encoder layer 2: g_tmp @ Wn2 + bn2 -> g_enc  (single 1536-row GEMM)
    {
        GArgs a = {tmp, nullptr, Wn2, nullptr, enc, nullptr, bn2, nullptr, QN + SN, 0, HDIM};
        gemm_k<0, 0, 0><<<dim3(HDIM / 64, (QN + SN) / 32, 1), 512, GEMM_SMEM_BYTES>>>(a);
    }

    // message-passing steps
    for (int t = 0; t < NSTEP; t++) {
        const float* Wm1t = Wm1 + (size_t)t * 2 * HDIM * HDIM;
        const float* Wm2t = Wm2 + (size_t)t * HDIM * HDIM;
        const float* bm1t = bm1 + (size_t)t * HDIM;
        const float* bm2t = bm2 + (size_t)t * HDIM;

        // A = s @ W1a ; B = s @ W1b   (fused via z)
        {
            GArgs a = {senc, senc, Wm1t, Wm1t + HDIM * HDIM, Abuf, Bbuf,
                       nullptr, nullptr, SN, SN, HDIM};
            gemm_k<0, 0, 0><<<dim3(HDIM / 64, SN / 32, 2), 512, GEMM_SMEM_BYTES>>>(a);
        }
        // masked relu aggregation (pre-divided by denom)
        hagg_k<<<SN, HDIM>>>(y, bm1t);
        // s += Hagg @ Wm2t + flag_i * bm2t
        {
            GArgs a = {Hg, nullptr, Wm2t, nullptr, senc, nullptr, bm2t, nullptr,
                       SN, 0, HDIM};
            gemm_k<0, 1, 1><<<dim3(HDIM / 64, SN / 32, 1), 512, GEMM_SMEM_BYTES>>>(a);
        }
    }

    // relation head: hq = q @ Wr1a + br1 ; hs = s @ Wr1b   (fused via z)
    {
        GArgs a = {qenc, senc, Wr1, Wr1 + HDIM * HDIM, hq, hs, br1, nullptr,
                   QN, SN, HDIM};
        gemm_k<0, 0, 0><<<dim3(HDIM / 64, QN / 32, 2), 512, GEMM_SMEM_BYTES>>>(a);
    }

    // scores
    scores_k<<<dim3(SN / 64, QN / 32, 1), 512, SCORE_SMEM_BYTES>>>(wr2, br2, out);
}